// round 7
// baseline (speedup 1.0000x reference)
#include <cuda_runtime.h>

namespace {
constexpr int P    = 32;
constexpr int Cin  = 9;
constexpr int H    = 64;
constexpr int OUTC = 128;
constexpr int FS   = 36;   // fT row stride (floats); 16B-aligned rows
constexpr int Q    = 4;    // polylines per CTA
constexpr float EPS = 1e-5f;
}

using ull = unsigned long long;

__device__ __forceinline__ ull fma2(ull a, ull b, ull c) {
  ull d;
  asm("fma.rn.f32x2 %0, %1, %2, %3;" : "=l"(d) : "l"(a), "l"(b), "l"(c));
  return d;
}
__device__ __forceinline__ ull dup2(float x) {
  ull d; unsigned u = __float_as_uint(x);
  asm("mov.b64 %0, {%1, %1};" : "=l"(d) : "r"(u));
  return d;
}
__device__ __forceinline__ ull pack2(float lo, float hi) {
  ull d;
  asm("mov.b64 %0, {%1, %2};" : "=l"(d)
      : "r"(__float_as_uint(lo)), "r"(__float_as_uint(hi)));
  return d;
}
__device__ __forceinline__ float2 unpk(ull v) {
  unsigned a, b;
  asm("mov.b64 {%0, %1}, %2;" : "=r"(a), "=r"(b) : "l"(v));
  return make_float2(__uint_as_float(a), __uint_as_float(b));
}
__device__ __forceinline__ void ldgw(const float* p, ull& a, ull& b) {
  asm("ld.global.nc.v2.u64 {%0, %1}, [%2];" : "=l"(a), "=l"(b) : "l"(p));
}
__device__ __forceinline__ void bn2(const float* g, const float* be,
                                    const float* rm, const float* rv,
                                    const float* b, int h, ull& A2v, ull& B2v) {
  float s0 = __ldg(&g[h])     * rsqrtf(__ldg(&rv[h])     + EPS);
  float s1 = __ldg(&g[h + 1]) * rsqrtf(__ldg(&rv[h + 1]) + EPS);
  float c0 = (__ldg(&b[h])     - __ldg(&rm[h]))     * s0 + __ldg(&be[h]);
  float c1 = (__ldg(&b[h + 1]) - __ldg(&rm[h + 1])) * s1 + __ldg(&be[h + 1]);
  A2v = pack2(s0, s1);
  B2v = pack2(c0, c1);
}

// 16 packed FMAs: one polyline's 4 points x 4 weight pairs
#define MMA_CORE(A, x0, x1, x2, x3)                                          \
  A[0][0]=fma2(x0,w01,A[0][0]); A[0][1]=fma2(x0,w23,A[0][1]);                \
  A[0][2]=fma2(x0,w45,A[0][2]); A[0][3]=fma2(x0,w67,A[0][3]);                \
  A[1][0]=fma2(x1,w01,A[1][0]); A[1][1]=fma2(x1,w23,A[1][1]);                \
  A[1][2]=fma2(x1,w45,A[1][2]); A[1][3]=fma2(x1,w67,A[1][3]);                \
  A[2][0]=fma2(x2,w01,A[2][0]); A[2][1]=fma2(x2,w23,A[2][1]);                \
  A[2][2]=fma2(x2,w45,A[2][2]); A[2][3]=fma2(x2,w67,A[2][3]);                \
  A[3][0]=fma2(x3,w01,A[3][0]); A[3][1]=fma2(x3,w23,A[3][1]);                \
  A[3][2]=fma2(x3,w45,A[3][2]); A[3][3]=fma2(x3,w67,A[3][3]);

#define MMA_F4(A, XV)                                                        \
  { ull x0=dup2((XV).x), x1=dup2((XV).y), x2=dup2((XV).z), x3=dup2((XV).w);  \
    MMA_CORE(A, x0, x1, x2, x3) }

__device__ __forceinline__ void epi_store(ull (&A)[4][4], const ull* A2, const ull* B2,
                                          float (*ft)[FS], int h0, int p0,
                                          float M0, float M1, float M2, float M3) {
#pragma unroll
  for (int j = 0; j < 4; j++) {
    float2 r0 = unpk(fma2(A[0][j], A2[j], B2[j]));
    float2 r1 = unpk(fma2(A[1][j], A2[j], B2[j]));
    float2 r2 = unpk(fma2(A[2][j], A2[j], B2[j]));
    float2 r3 = unpk(fma2(A[3][j], A2[j], B2[j]));
    *(float4*)&ft[h0 + 2 * j][p0] =
      make_float4(fmaxf(r0.x, 0.f) * M0, fmaxf(r1.x, 0.f) * M1,
                  fmaxf(r2.x, 0.f) * M2, fmaxf(r3.x, 0.f) * M3);
    *(float4*)&ft[h0 + 2 * j + 1][p0] =
      make_float4(fmaxf(r0.y, 0.f) * M0, fmaxf(r1.y, 0.f) * M1,
                  fmaxf(r2.y, 0.f) * M2, fmaxf(r3.y, 0.f) * M3);
  }
}

__global__ void __launch_bounds__(64, 5)
pnet_kernel(const float* __restrict__ poly,
            const void*  __restrict__ mask,
            const float* __restrict__ pre_w, const float* __restrict__ pre_b,
            const float* __restrict__ pre_g, const float* __restrict__ pre_be,
            const float* __restrict__ pre_rm, const float* __restrict__ pre_rv,
            const float* __restrict__ m1_w,  const float* __restrict__ m1_b,
            const float* __restrict__ m1_g,  const float* __restrict__ m1_be,
            const float* __restrict__ m1_rm, const float* __restrict__ m1_rv,
            const float* __restrict__ m2_w,  const float* __restrict__ m2_b,
            const float* __restrict__ m2_g,  const float* __restrict__ m2_be,
            const float* __restrict__ m2_rm, const float* __restrict__ m2_rv,
            const float* __restrict__ o1_w,  const float* __restrict__ o1_b,
            const float* __restrict__ o2_w,  const float* __restrict__ o2_b,
            float* __restrict__ out, int n_poly)
{
  // 4 polylines per CTA; one weight fetch feeds all four.
  __shared__ __align__(16) float fT[Q][H][FS];     // also overlaid as pts buffer
  __shared__ float  mk[Q][P];
  __shared__ __align__(16) float4 pooled4[H];      // interleaved {q0,q1,q2,q3}
  __shared__ float  pctr[Q][H];
  __shared__ __align__(16) float4 feat4[H];
  __shared__ __align__(16) float4 hid4[H];
  __shared__ int    s_mode;
  __shared__ int    s_valid[Q];

  const int blk = blockIdx.x;          // polylines Q*blk .. Q*blk+3
  const int tid = threadIdx.x;         // 0..63
  const int cg  = tid >> 3;            // warp0 -> ch 0..31, warp1 -> 32..63
  const int pg  = tid & 7;
  const int h0  = cg * 8;
  const int p0  = pg * 4;
  const int pbase = Q * blk;

  // ---- mask dtype detection (int32 vs float32 vs byte) ----
  if (tid == 0) {
    const unsigned* w32 = (const unsigned*)mask;
    bool big = false, allf = true;
    #pragma unroll
    for (int i = 0; i < 32; i++) {
      unsigned v = w32[i];
      big  |= (v > 1u);
      allf &= (v == 0u || v == 0x3f800000u);
    }
    s_mode = big ? (allf ? 1 : 2) : 0;
  }
  __syncthreads();
  const int mode = s_mode;

  // ---- load points (into fT overlay) + masks ----
  float* ptsf = (float*)fT;            // ptsf[q*288 + p*9 + c], 4608B << fT size
  {
    const long long tot = (long long)n_poly * (P * Cin);
    long long base = (long long)pbase * (P * Cin);
    for (int i = tid; i < Q * P * Cin; i += 64) {
      long long gi = base + i;
      ptsf[i] = (gi < tot) ? poly[gi] : 0.f;
    }
  }
  {
    const long long mtot = (long long)n_poly * P;
    #pragma unroll
    for (int rep = 0; rep < 2; rep++) {
      int i = tid + rep * 64;
      int q = i >> 5, t = i & 31;
      long long gi = (long long)(pbase + q) * P + t;
      float mv = 0.f;
      if (gi < mtot) {
        if (mode == 2)      mv = ((const unsigned char*)mask)[gi] ? 1.f : 0.f;
        else if (mode == 1) mv = (((const float*)mask)[gi] != 0.f) ? 1.f : 0.f;
        else                mv = ((const int*)mask)[gi] ? 1.f : 0.f;
      }
      mk[q][t] = mv;
      unsigned bal = __ballot_sync(0xffffffffu, mv != 0.f);
      if (t == 0) s_valid[q] = (bal != 0u) ? 1 : 0;
    }
  }
  __syncthreads();

  ull accA[4][4], accB[4][4], accC[4][4], accD[4][4];
  ull w01, w23, w45, w67;
  ull A2[4], B2[4];

  // ================= pre layer: [P,9] @ [9,64], 4 polylines ================
  #pragma unroll
  for (int i = 0; i < 4; i++)
    #pragma unroll
    for (int j = 0; j < 4; j++) {
      accA[i][j] = 0ull; accB[i][j] = 0ull;
      accC[i][j] = 0ull; accD[i][j] = 0ull;
    }

  #pragma unroll 3
  for (int k = 0; k < Cin; k++) {
    const float* wr = pre_w + k * H + h0;
    ldgw(wr, w01, w23);
    ldgw(wr + 4, w45, w67);
    #define PRE_X(A, q)                                                      \
      { ull x0 = dup2(ptsf[(q)*288 + (p0+0)*9 + k]);                         \
        ull x1 = dup2(ptsf[(q)*288 + (p0+1)*9 + k]);                         \
        ull x2 = dup2(ptsf[(q)*288 + (p0+2)*9 + k]);                         \
        ull x3 = dup2(ptsf[(q)*288 + (p0+3)*9 + k]);                         \
        MMA_CORE(A, x0, x1, x2, x3) }
    PRE_X(accA, 0) PRE_X(accB, 1) PRE_X(accC, 2) PRE_X(accD, 3)
    #undef PRE_X
  }
  #pragma unroll
  for (int j = 0; j < 4; j++) bn2(pre_g, pre_be, pre_rm, pre_rv, pre_b, h0 + 2 * j, A2[j], B2[j]);
  __syncthreads();   // all ptsf reads done before fT overwrite
  epi_store(accA, A2, B2, fT[0], h0, p0, mk[0][p0], mk[0][p0+1], mk[0][p0+2], mk[0][p0+3]);
  epi_store(accB, A2, B2, fT[1], h0, p0, mk[1][p0], mk[1][p0+1], mk[1][p0+2], mk[1][p0+3]);
  epi_store(accC, A2, B2, fT[2], h0, p0, mk[2][p0], mk[2][p0+1], mk[2][p0+2], mk[2][p0+3]);
  epi_store(accD, A2, B2, fT[3], h0, p0, mk[3][p0], mk[3][p0+1], mk[3][p0+2], mk[3][p0+3]);
  __syncthreads();

  // ===== max-pool over points (channel = tid), interleaved output ==========
  {
    float4 pm;
    #pragma unroll
    for (int q = 0; q < Q; q++) {
      const float4* row = (const float4*)&fT[q][tid][0];
      float m = 0.f;
      #pragma unroll
      for (int g = 0; g < 8; g++) {
        float4 v = row[g];
        m = fmaxf(m, fmaxf(fmaxf(v.x, v.y), fmaxf(v.z, v.w)));
      }
      ((float*)&pm)[q] = m;
    }
    pooled4[tid] = pm;
  }
  __syncthreads();

  // pctr = pooled @ m1_w[64:128,:], 4 polylines packed in 2 f32x2 lanes
  {
    ull a01 = 0ull, a23 = 0ull, b01 = 0ull, b23 = 0ull;
    #pragma unroll 4
    for (int k = 0; k < H; k += 2) {
      float wv0 = __ldg(&m1_w[(H + k) * H + tid]);
      float wv1 = __ldg(&m1_w[(H + k + 1) * H + tid]);
      ulonglong2 xa = *(const ulonglong2*)&pooled4[k];
      ulonglong2 xb = *(const ulonglong2*)&pooled4[k + 1];
      ull d0 = dup2(wv0), d1 = dup2(wv1);
      a01 = fma2(xa.x, d0, a01); a23 = fma2(xa.y, d0, a23);
      b01 = fma2(xb.x, d1, b01); b23 = fma2(xb.y, d1, b23);
    }
    ull one = dup2(1.f);
    a01 = fma2(b01, one, a01); a23 = fma2(b23, one, a23);
    float2 r01 = unpk(a01), r23 = unpk(a23);
    pctr[0][tid] = r01.x; pctr[1][tid] = r01.y;
    pctr[2][tid] = r23.x; pctr[3][tid] = r23.y;
  }
  __syncthreads();

  // ================= m1: [P,64] @ m1_w[0:64,:] + pctr ======================
  #pragma unroll
  for (int j = 0; j < 4; j++) {
    float2 c;
    c = *(const float2*)&pctr[0][h0 + 2*j]; ull cc = pack2(c.x, c.y);
    accA[0][j]=cc; accA[1][j]=cc; accA[2][j]=cc; accA[3][j]=cc;
    c = *(const float2*)&pctr[1][h0 + 2*j]; cc = pack2(c.x, c.y);
    accB[0][j]=cc; accB[1][j]=cc; accB[2][j]=cc; accB[3][j]=cc;
    c = *(const float2*)&pctr[2][h0 + 2*j]; cc = pack2(c.x, c.y);
    accC[0][j]=cc; accC[1][j]=cc; accC[2][j]=cc; accC[3][j]=cc;
    c = *(const float2*)&pctr[3][h0 + 2*j]; cc = pack2(c.x, c.y);
    accD[0][j]=cc; accD[1][j]=cc; accD[2][j]=cc; accD[3][j]=cc;
  }
  #pragma unroll 2
  for (int k = 0; k < H; k++) {
    const float* wr = m1_w + k * H + h0;
    ldgw(wr, w01, w23);
    ldgw(wr + 4, w45, w67);
    float4 xv;
    xv = *(const float4*)&fT[0][k][p0]; MMA_F4(accA, xv)
    xv = *(const float4*)&fT[1][k][p0]; MMA_F4(accB, xv)
    xv = *(const float4*)&fT[2][k][p0]; MMA_F4(accC, xv)
    xv = *(const float4*)&fT[3][k][p0]; MMA_F4(accD, xv)
  }
  #pragma unroll
  for (int j = 0; j < 4; j++) bn2(m1_g, m1_be, m1_rm, m1_rv, m1_b, h0 + 2 * j, A2[j], B2[j]);
  __syncthreads();   // all fT reads done before overwrite
  epi_store(accA, A2, B2, fT[0], h0, p0, 1.f, 1.f, 1.f, 1.f);
  epi_store(accB, A2, B2, fT[1], h0, p0, 1.f, 1.f, 1.f, 1.f);
  epi_store(accC, A2, B2, fT[2], h0, p0, 1.f, 1.f, 1.f, 1.f);
  epi_store(accD, A2, B2, fT[3], h0, p0, 1.f, 1.f, 1.f, 1.f);
  __syncthreads();

  // ================= m2: [P,64] @ [64,64], masked ==========================
  #pragma unroll
  for (int i = 0; i < 4; i++)
    #pragma unroll
    for (int j = 0; j < 4; j++) {
      accA[i][j] = 0ull; accB[i][j] = 0ull;
      accC[i][j] = 0ull; accD[i][j] = 0ull;
    }
  #pragma unroll 2
  for (int k = 0; k < H; k++) {
    const float* wr = m2_w + k * H + h0;
    ldgw(wr, w01, w23);
    ldgw(wr + 4, w45, w67);
    float4 xv;
    xv = *(const float4*)&fT[0][k][p0]; MMA_F4(accA, xv)
    xv = *(const float4*)&fT[1][k][p0]; MMA_F4(accB, xv)
    xv = *(const float4*)&fT[2][k][p0]; MMA_F4(accC, xv)
    xv = *(const float4*)&fT[3][k][p0]; MMA_F4(accD, xv)
  }
  #pragma unroll
  for (int j = 0; j < 4; j++) bn2(m2_g, m2_be, m2_rm, m2_rv, m2_b, h0 + 2 * j, A2[j], B2[j]);
  __syncthreads();
  epi_store(accA, A2, B2, fT[0], h0, p0, mk[0][p0], mk[0][p0+1], mk[0][p0+2], mk[0][p0+3]);
  epi_store(accB, A2, B2, fT[1], h0, p0, mk[1][p0], mk[1][p0+1], mk[1][p0+2], mk[1][p0+3]);
  epi_store(accC, A2, B2, fT[2], h0, p0, mk[2][p0], mk[2][p0+1], mk[2][p0+2], mk[2][p0+3]);
  epi_store(accD, A2, B2, fT[3], h0, p0, mk[3][p0], mk[3][p0+1], mk[3][p0+2], mk[3][p0+3]);
  __syncthreads();

  // ================= feat = max-pool over points (interleaved) =============
  {
    float4 pm;
    #pragma unroll
    for (int q = 0; q < Q; q++) {
      const float4* row = (const float4*)&fT[q][tid][0];
      float m = 0.f;
      #pragma unroll
      for (int g = 0; g < 8; g++) {
        float4 v = row[g];
        m = fmaxf(m, fmaxf(fmaxf(v.x, v.y), fmaxf(v.z, v.w)));
      }
      ((float*)&pm)[q] = m;
    }
    feat4[tid] = pm;
  }
  __syncthreads();

  // ================= head layer 1: hid = relu(feat @ o1_w + o1_b) ==========
  {
    ull a01 = dup2(__ldg(&o1_b[tid])), a23 = a01;
    ull b01 = 0ull, b23 = 0ull;
    #pragma unroll 4
    for (int k = 0; k < H; k += 2) {
      float wv0 = __ldg(&o1_w[k * H + tid]);
      float wv1 = __ldg(&o1_w[(k + 1) * H + tid]);
      ulonglong2 xa = *(const ulonglong2*)&feat4[k];
      ulonglong2 xb = *(const ulonglong2*)&feat4[k + 1];
      ull d0 = dup2(wv0), d1 = dup2(wv1);
      a01 = fma2(xa.x, d0, a01); a23 = fma2(xa.y, d0, a23);
      b01 = fma2(xb.x, d1, b01); b23 = fma2(xb.y, d1, b23);
    }
    ull one = dup2(1.f);
    a01 = fma2(b01, one, a01); a23 = fma2(b23, one, a23);
    float2 r01 = unpk(a01), r23 = unpk(a23);
    hid4[tid] = make_float4(fmaxf(r01.x, 0.f), fmaxf(r01.y, 0.f),
                            fmaxf(r23.x, 0.f), fmaxf(r23.y, 0.f));
  }
  __syncthreads();

  // ================= head layer 2: out = hid @ o2_w + o2_b =================
  {
    float vf0 = s_valid[0] ? 1.f : 0.f;
    float vf1 = s_valid[1] ? 1.f : 0.f;
    float vf2 = s_valid[2] ? 1.f : 0.f;
    float vf3 = s_valid[3] ? 1.f : 0.f;
    #pragma unroll
    for (int rep = 0; rep < 2; rep++) {
      int j = tid + rep * 64;
      ull a01 = dup2(__ldg(&o2_b[j])), a23 = a01;
      ull b01 = 0ull, b23 = 0ull;
      #pragma unroll 4
      for (int k = 0; k < H; k += 2) {
        float wv0 = __ldg(&o2_w[k * OUTC + j]);
        float wv1 = __ldg(&o2_w[(k + 1) * OUTC + j]);
        ulonglong2 xa = *(const ulonglong2*)&hid4[k];
        ulonglong2 xb = *(const ulonglong2*)&hid4[k + 1];
        ull d0 = dup2(wv0), d1 = dup2(wv1);
        a01 = fma2(xa.x, d0, a01); a23 = fma2(xa.y, d0, a23);
        b01 = fma2(xb.x, d1, b01); b23 = fma2(xb.y, d1, b23);
      }
      ull one = dup2(1.f);
      a01 = fma2(b01, one, a01); a23 = fma2(b23, one, a23);
      float2 r01 = unpk(a01), r23 = unpk(a23);
      long long ob = (long long)pbase * OUTC + j;
      if (pbase + 0 < n_poly) out[ob]            = r01.x * vf0;
      if (pbase + 1 < n_poly) out[ob + OUTC]     = r01.y * vf1;
      if (pbase + 2 < n_poly) out[ob + 2 * OUTC] = r23.x * vf2;
      if (pbase + 3 < n_poly) out[ob + 3 * OUTC] = r23.y * vf3;
    }
  }
}

extern "C" void kernel_launch(void* const* d_in, const int* in_sizes, int n_in,
                              void* d_out, int out_size)
{
  (void)in_sizes; (void)n_in;
  const int n_poly = out_size / OUTC;   // B*N = 16384
  const int nblk = (n_poly + Q - 1) / Q;
  pnet_kernel<<<nblk, 64>>>(
      (const float*)d_in[0],  d_in[1],
      (const float*)d_in[2],  (const float*)d_in[3],
      (const float*)d_in[4],  (const float*)d_in[5],
      (const float*)d_in[6],  (const float*)d_in[7],
      (const float*)d_in[8],  (const float*)d_in[9],
      (const float*)d_in[10], (const float*)d_in[11],
      (const float*)d_in[12], (const float*)d_in[13],
      (const float*)d_in[14], (const float*)d_in[15],
      (const float*)d_in[16], (const float*)d_in[17],
      (const float*)d_in[18], (const float*)d_in[19],
      (const float*)d_in[20], (const float*)d_in[21],
      (const float*)d_in[22], (const float*)d_in[23],
      (float*)d_out, n_poly);
}

// round 9
// speedup vs baseline: 1.0852x; 1.0852x over previous
#include <cuda_runtime.h>

namespace {
constexpr int P    = 32;
constexpr int Cin  = 9;
constexpr int H    = 64;
constexpr int OUTC = 128;
constexpr int FS   = 36;   // fT row stride (floats); 16B-aligned rows
}
constexpr float EPS = 1e-5f;

using ull = unsigned long long;

struct SB {
  float fT[2][H][FS];      // activations, [channel][point]
  float wS[2][H][H];       // staged weights: [0]=m1_w rows 0..63, [1]=m2_w
  float pts[2][P][12];
  float mk[2][P];
  float pooled[2][H];
  float pctr[2][H];
  float feat[2][H];
  float hid[2][H];
  int   s_mode;
  int   s_valid[2];
};
constexpr unsigned SMEM_BYTES = sizeof(SB);   // ~56.6 KB

__device__ __forceinline__ ull fma2(ull a, ull b, ull c) {
  ull d;
  asm("fma.rn.f32x2 %0, %1, %2, %3;" : "=l"(d) : "l"(a), "l"(b), "l"(c));
  return d;
}
__device__ __forceinline__ ull dup2(float x) {
  ull d; unsigned u = __float_as_uint(x);
  asm("mov.b64 %0, {%1, %1};" : "=l"(d) : "r"(u));
  return d;
}
__device__ __forceinline__ ull pack2(float lo, float hi) {
  ull d;
  asm("mov.b64 %0, {%1, %2};" : "=l"(d)
      : "r"(__float_as_uint(lo)), "r"(__float_as_uint(hi)));
  return d;
}
__device__ __forceinline__ float2 unpk(ull v) {
  unsigned a, b;
  asm("mov.b64 {%0, %1}, %2;" : "=r"(a), "=r"(b) : "l"(v));
  return make_float2(__uint_as_float(a), __uint_as_float(b));
}
__device__ __forceinline__ void ldgw(const float* p, ull& a, ull& b) {
  asm("ld.global.nc.v2.u64 {%0, %1}, [%2];" : "=l"(a), "=l"(b) : "l"(p));
}
__device__ __forceinline__ void bn2(const float* g, const float* be,
                                    const float* rm, const float* rv,
                                    const float* b, int h, ull& A2v, ull& B2v) {
  float s0 = __ldg(&g[h])     * rsqrtf(__ldg(&rv[h])     + EPS);
  float s1 = __ldg(&g[h + 1]) * rsqrtf(__ldg(&rv[h + 1]) + EPS);
  float c0 = (__ldg(&b[h])     - __ldg(&rm[h]))     * s0 + __ldg(&be[h]);
  float c1 = (__ldg(&b[h + 1]) - __ldg(&rm[h + 1])) * s1 + __ldg(&be[h + 1]);
  A2v = pack2(s0, s1);
  B2v = pack2(c0, c1);
}

// 16 packed FMAs for one polyline's 4 points against 4 weight pairs
#define MMA_STEP(A, X0, X1, X2, X3)                                           \
  {                                                                           \
    A[0][0] = fma2(X0, w01, A[0][0]); A[0][1] = fma2(X0, w23, A[0][1]);       \
    A[0][2] = fma2(X0, w45, A[0][2]); A[0][3] = fma2(X0, w67, A[0][3]);       \
    A[1][0] = fma2(X1, w01, A[1][0]); A[1][1] = fma2(X1, w23, A[1][1]);       \
    A[1][2] = fma2(X1, w45, A[1][2]); A[1][3] = fma2(X1, w67, A[1][3]);       \
    A[2][0] = fma2(X2, w01, A[2][0]); A[2][1] = fma2(X2, w23, A[2][1]);       \
    A[2][2] = fma2(X2, w45, A[2][2]); A[2][3] = fma2(X2, w67, A[2][3]);       \
    A[3][0] = fma2(X3, w01, A[3][0]); A[3][1] = fma2(X3, w23, A[3][1]);       \
    A[3][2] = fma2(X3, w45, A[3][2]); A[3][3] = fma2(X3, w67, A[3][3]);       \
  }

__global__ void __launch_bounds__(64)
pnet_kernel(const float* __restrict__ poly,
            const void*  __restrict__ mask,
            const float* __restrict__ pre_w, const float* __restrict__ pre_b,
            const float* __restrict__ pre_g, const float* __restrict__ pre_be,
            const float* __restrict__ pre_rm, const float* __restrict__ pre_rv,
            const float* __restrict__ m1_w,  const float* __restrict__ m1_b,
            const float* __restrict__ m1_g,  const float* __restrict__ m1_be,
            const float* __restrict__ m1_rm, const float* __restrict__ m1_rv,
            const float* __restrict__ m2_w,  const float* __restrict__ m2_b,
            const float* __restrict__ m2_g,  const float* __restrict__ m2_be,
            const float* __restrict__ m2_rm, const float* __restrict__ m2_rv,
            const float* __restrict__ o1_w,  const float* __restrict__ o1_b,
            const float* __restrict__ o2_w,  const float* __restrict__ o2_b,
            float* __restrict__ out)
{
  extern __shared__ __align__(16) unsigned char smem_raw[];
  SB* sb = (SB*)smem_raw;

  const int blk = blockIdx.x;          // handles polylines 2*blk, 2*blk+1
  const int tid = threadIdx.x;         // 0..63
  const int cg  = tid >> 3;            // warp0 -> ch 0..31, warp1 -> 32..63
  const int pg  = tid & 7;
  const int h0  = cg * 8;
  const int p0  = pg * 4;

  // ---- stage m1_w (rows 0..63) and m2_w into smem (float4 copies) ----
  {
    float4*       dst = (float4*)sb->wS;
    const float4* s1  = (const float4*)m1_w;   // first 1024 float4 = rows 0..63
    const float4* s2  = (const float4*)m2_w;
    #pragma unroll
    for (int i = 0; i < 16; i++) {
      int idx = tid + i * 64;
      dst[idx]        = __ldg(s1 + idx);
      dst[1024 + idx] = __ldg(s2 + idx);
    }
  }

  // ---- mask dtype detection (int32 vs float32 vs byte) ----
  if (tid == 0) {
    const unsigned* w32 = (const unsigned*)mask;
    bool big = false, allf = true;
    #pragma unroll
    for (int i = 0; i < 32; i++) {
      unsigned v = w32[i];
      big  |= (v > 1u);
      allf &= (v == 0u || v == 0x3f800000u);
    }
    sb->s_mode = big ? (allf ? 1 : 2) : 0;
  }
  __syncthreads();
  const int mode = sb->s_mode;

  // ---- load points + mask for both polylines ----
  {
    const float* pp = poly + (long long)(2 * blk) * (P * Cin);
    for (int i = tid; i < 2 * P * Cin; i += 64) {
      int q = i / (P * Cin), r = i % (P * Cin);
      sb->pts[q][r / Cin][r % Cin] = pp[i];
    }
  }
  {
    int q = tid >> 5, t = tid & 31;
    int gi = (2 * blk + q) * P + t;
    float mv;
    if (mode == 2)      mv = ((const unsigned char*)mask)[gi] ? 1.f : 0.f;
    else if (mode == 1) mv = (((const float*)mask)[gi] != 0.f) ? 1.f : 0.f;
    else                mv = ((const int*)mask)[gi] ? 1.f : 0.f;
    sb->mk[q][t] = mv;
    unsigned bal = __ballot_sync(0xffffffffu, mv != 0.f);
    if (t == 0) sb->s_valid[q] = (bal != 0u) ? 1 : 0;
  }
  __syncthreads();

  ull acc0[4][4], acc1[4][4];
  ull w01, w23, w45, w67;
  ull A2[4], B2[4];

  // ================= pre layer: [P,9] @ [9,64], both polylines =============
  #pragma unroll
  for (int i = 0; i < 4; i++)
    #pragma unroll
    for (int j = 0; j < 4; j++) { acc0[i][j] = 0ull; acc1[i][j] = 0ull; }

  #pragma unroll
  for (int k = 0; k < Cin; k++) {
    const float* wr = pre_w + k * H + h0;
    ldgw(wr, w01, w23);
    ldgw(wr + 4, w45, w67);
    ull x0 = dup2(sb->pts[0][p0 + 0][k]);
    ull x1 = dup2(sb->pts[0][p0 + 1][k]);
    ull x2 = dup2(sb->pts[0][p0 + 2][k]);
    ull x3 = dup2(sb->pts[0][p0 + 3][k]);
    MMA_STEP(acc0, x0, x1, x2, x3)
    x0 = dup2(sb->pts[1][p0 + 0][k]);
    x1 = dup2(sb->pts[1][p0 + 1][k]);
    x2 = dup2(sb->pts[1][p0 + 2][k]);
    x3 = dup2(sb->pts[1][p0 + 3][k]);
    MMA_STEP(acc1, x0, x1, x2, x3)
  }
  #pragma unroll
  for (int j = 0; j < 4; j++) bn2(pre_g, pre_be, pre_rm, pre_rv, pre_b, h0 + 2 * j, A2[j], B2[j]);
  #pragma unroll
  for (int q = 0; q < 2; q++) {
    ull (*ac)[4] = q ? acc1 : acc0;
    float mv0 = sb->mk[q][p0],     mv1 = sb->mk[q][p0 + 1];
    float mv2 = sb->mk[q][p0 + 2], mv3 = sb->mk[q][p0 + 3];
    #pragma unroll
    for (int j = 0; j < 4; j++) {
      float2 r0 = unpk(fma2(ac[0][j], A2[j], B2[j]));
      float2 r1 = unpk(fma2(ac[1][j], A2[j], B2[j]));
      float2 r2 = unpk(fma2(ac[2][j], A2[j], B2[j]));
      float2 r3 = unpk(fma2(ac[3][j], A2[j], B2[j]));
      *(float4*)&sb->fT[q][h0 + 2 * j][p0] =
        make_float4(fmaxf(r0.x, 0.f) * mv0, fmaxf(r1.x, 0.f) * mv1,
                    fmaxf(r2.x, 0.f) * mv2, fmaxf(r3.x, 0.f) * mv3);
      *(float4*)&sb->fT[q][h0 + 2 * j + 1][p0] =
        make_float4(fmaxf(r0.y, 0.f) * mv0, fmaxf(r1.y, 0.f) * mv1,
                    fmaxf(r2.y, 0.f) * mv2, fmaxf(r3.y, 0.f) * mv3);
    }
  }
  __syncthreads();

  // ========= max-pool over points (channel = tid, both polylines) =========
  #pragma unroll
  for (int q = 0; q < 2; q++) {
    const float4* row = (const float4*)&sb->fT[q][tid][0];
    float m = 0.f;
    #pragma unroll
    for (int g = 0; g < 8; g++) {
      float4 v = row[g];
      m = fmaxf(m, fmaxf(fmaxf(v.x, v.y), fmaxf(v.z, v.w)));
    }
    sb->pooled[q][tid] = m;
  }
  __syncthreads();

  // pctr = pooled @ m1_w[64:128,:]  (both polylines share weight loads)
  {
    ull a = 0ull;
    #pragma unroll 8
    for (int k = 0; k < H; k++) {
      float wv = __ldg(&m1_w[(H + k) * H + tid]);
      a = fma2(pack2(sb->pooled[0][k], sb->pooled[1][k]), dup2(wv), a);
    }
    float2 r = unpk(a);
    sb->pctr[0][tid] = r.x;
    sb->pctr[1][tid] = r.y;
  }
  __syncthreads();

  // ================= m1: [P,64] @ wS[0] + pctr  (all-smem operands) ========
  #pragma unroll
  for (int j = 0; j < 4; j++) {
    float2 c0 = *(const float2*)&sb->pctr[0][h0 + 2 * j];
    float2 c1 = *(const float2*)&sb->pctr[1][h0 + 2 * j];
    ull p0c = pack2(c0.x, c0.y), p1c = pack2(c1.x, c1.y);
    acc0[0][j] = p0c; acc0[1][j] = p0c; acc0[2][j] = p0c; acc0[3][j] = p0c;
    acc1[0][j] = p1c; acc1[1][j] = p1c; acc1[2][j] = p1c; acc1[3][j] = p1c;
  }
  #pragma unroll 4
  for (int k = 0; k < H; k++) {
    ulonglong2 wa = *(const ulonglong2*)&sb->wS[0][k][h0];
    ulonglong2 wb = *(const ulonglong2*)&sb->wS[0][k][h0 + 4];
    w01 = wa.x; w23 = wa.y; w45 = wb.x; w67 = wb.y;
    float4 xv = *(const float4*)&sb->fT[0][k][p0];
    ull x0 = dup2(xv.x), x1 = dup2(xv.y), x2 = dup2(xv.z), x3 = dup2(xv.w);
    MMA_STEP(acc0, x0, x1, x2, x3)
    xv = *(const float4*)&sb->fT[1][k][p0];
    x0 = dup2(xv.x); x1 = dup2(xv.y); x2 = dup2(xv.z); x3 = dup2(xv.w);
    MMA_STEP(acc1, x0, x1, x2, x3)
  }
  #pragma unroll
  for (int j = 0; j < 4; j++) bn2(m1_g, m1_be, m1_rm, m1_rv, m1_b, h0 + 2 * j, A2[j], B2[j]);
  {
    float4 s[2][4][2];
    #pragma unroll
    for (int q = 0; q < 2; q++) {
      ull (*ac)[4] = q ? acc1 : acc0;
      #pragma unroll
      for (int j = 0; j < 4; j++) {
        float2 r0 = unpk(fma2(ac[0][j], A2[j], B2[j]));
        float2 r1 = unpk(fma2(ac[1][j], A2[j], B2[j]));
        float2 r2 = unpk(fma2(ac[2][j], A2[j], B2[j]));
        float2 r3 = unpk(fma2(ac[3][j], A2[j], B2[j]));
        s[q][j][0] = make_float4(fmaxf(r0.x, 0.f), fmaxf(r1.x, 0.f),
                                 fmaxf(r2.x, 0.f), fmaxf(r3.x, 0.f));
        s[q][j][1] = make_float4(fmaxf(r0.y, 0.f), fmaxf(r1.y, 0.f),
                                 fmaxf(r2.y, 0.f), fmaxf(r3.y, 0.f));
      }
    }
    __syncthreads();   // all fT reads done; safe to overwrite
    #pragma unroll
    for (int q = 0; q < 2; q++)
      #pragma unroll
      for (int j = 0; j < 4; j++) {
        *(float4*)&sb->fT[q][h0 + 2 * j][p0]     = s[q][j][0];
        *(float4*)&sb->fT[q][h0 + 2 * j + 1][p0] = s[q][j][1];
      }
  }
  __syncthreads();

  // ================= m2: [P,64] @ wS[1], masked  (all-smem operands) =======
  #pragma unroll
  for (int i = 0; i < 4; i++)
    #pragma unroll
    for (int j = 0; j < 4; j++) { acc0[i][j] = 0ull; acc1[i][j] = 0ull; }

  #pragma unroll 4
  for (int k = 0; k < H; k++) {
    ulonglong2 wa = *(const ulonglong2*)&sb->wS[1][k][h0];
    ulonglong2 wb = *(const ulonglong2*)&sb->wS[1][k][h0 + 4];
    w01 = wa.x; w23 = wa.y; w45 = wb.x; w67 = wb.y;
    float4 xv = *(const float4*)&sb->fT[0][k][p0];
    ull x0 = dup2(xv.x), x1 = dup2(xv.y), x2 = dup2(xv.z), x3 = dup2(xv.w);
    MMA_STEP(acc0, x0, x1, x2, x3)
    xv = *(const float4*)&sb->fT[1][k][p0];
    x0 = dup2(xv.x); x1 = dup2(xv.y); x2 = dup2(xv.z); x3 = dup2(xv.w);
    MMA_STEP(acc1, x0, x1, x2, x3)
  }
  #pragma unroll
  for (int j = 0; j < 4; j++) bn2(m2_g, m2_be, m2_rm, m2_rv, m2_b, h0 + 2 * j, A2[j], B2[j]);
  {
    float4 s[2][4][2];
    #pragma unroll
    for (int q = 0; q < 2; q++) {
      ull (*ac)[4] = q ? acc1 : acc0;
      float mv0 = sb->mk[q][p0],     mv1 = sb->mk[q][p0 + 1];
      float mv2 = sb->mk[q][p0 + 2], mv3 = sb->mk[q][p0 + 3];
      #pragma unroll
      for (int j = 0; j < 4; j++) {
        float2 r0 = unpk(fma2(ac[0][j], A2[j], B2[j]));
        float2 r1 = unpk(fma2(ac[1][j], A2[j], B2[j]));
        float2 r2 = unpk(fma2(ac[2][j], A2[j], B2[j]));
        float2 r3 = unpk(fma2(ac[3][j], A2[j], B2[j]));
        s[q][j][0] = make_float4(fmaxf(r0.x, 0.f) * mv0, fmaxf(r1.x, 0.f) * mv1,
                                 fmaxf(r2.x, 0.f) * mv2, fmaxf(r3.x, 0.f) * mv3);
        s[q][j][1] = make_float4(fmaxf(r0.y, 0.f) * mv0, fmaxf(r1.y, 0.f) * mv1,
                                 fmaxf(r2.y, 0.f) * mv2, fmaxf(r3.y, 0.f) * mv3);
      }
    }
    __syncthreads();
    #pragma unroll
    for (int q = 0; q < 2; q++)
      #pragma unroll
      for (int j = 0; j < 4; j++) {
        *(float4*)&sb->fT[q][h0 + 2 * j][p0]     = s[q][j][0];
        *(float4*)&sb->fT[q][h0 + 2 * j + 1][p0] = s[q][j][1];
      }
  }
  __syncthreads();

  // ================= feat = max-pool over points =================
  #pragma unroll
  for (int q = 0; q < 2; q++) {
    const float4* row = (const float4*)&sb->fT[q][tid][0];
    float m = 0.f;
    #pragma unroll
    for (int g = 0; g < 8; g++) {
      float4 v = row[g];
      m = fmaxf(m, fmaxf(fmaxf(v.x, v.y), fmaxf(v.z, v.w)));
    }
    sb->feat[q][tid] = m;
  }
  __syncthreads();

  // ================= head (weight loads shared across polylines) ===========
  {
    ull a = dup2(__ldg(&o1_b[tid]));
    #pragma unroll 8
    for (int k = 0; k < H; k++) {
      float wv = __ldg(&o1_w[k * H + tid]);
      a = fma2(pack2(sb->feat[0][k], sb->feat[1][k]), dup2(wv), a);
    }
    float2 r = unpk(a);
    sb->hid[0][tid] = fmaxf(r.x, 0.f);
    sb->hid[1][tid] = fmaxf(r.y, 0.f);
  }
  __syncthreads();

  {
    float vf0 = sb->s_valid[0] ? 1.f : 0.f;
    float vf1 = sb->s_valid[1] ? 1.f : 0.f;
    #pragma unroll
    for (int rep = 0; rep < 2; rep++) {
      int j = tid + rep * 64;
      ull a = dup2(__ldg(&o2_b[j]));
      #pragma unroll 8
      for (int k = 0; k < H; k++) {
        float wv = __ldg(&o2_w[k * OUTC + j]);
        a = fma2(pack2(sb->hid[0][k], sb->hid[1][k]), dup2(wv), a);
      }
      float2 r = unpk(a);
      out[(long long)(2 * blk) * OUTC + j]     = r.x * vf0;
      out[(long long)(2 * blk + 1) * OUTC + j] = r.y * vf1;
    }
  }
}

extern "C" void kernel_launch(void* const* d_in, const int* in_sizes, int n_in,
                              void* d_out, int out_size)
{
  (void)in_sizes; (void)n_in;
  const int n_poly = out_size / OUTC;   // B*N = 16384 (even)
  cudaFuncSetAttribute(pnet_kernel,
                       cudaFuncAttributeMaxDynamicSharedMemorySize, SMEM_BYTES);
  pnet_kernel<<<n_poly / 2, 64, SMEM_BYTES>>>(
      (const float*)d_in[0],  d_in[1],
      (const float*)d_in[2],  (const float*)d_in[3],
      (const float*)d_in[4],  (const float*)d_in[5],
      (const float*)d_in[6],  (const float*)d_in[7],
      (const float*)d_in[8],  (const float*)d_in[9],
      (const float*)d_in[10], (const float*)d_in[11],
      (const float*)d_in[12], (const float*)d_in[13],
      (const float*)d_in[14], (const float*)d_in[15],
      (const float*)d_in[16], (const float*)d_in[17],
      (const float*)d_in[18], (const float*)d_in[19],
      (const float*)d_in[20], (const float*)d_in[21],
      (const float*)d_in[22], (const float*)d_in[23],
      (float*)d_out);
}

// round 12
// speedup vs baseline: 1.1952x; 1.1014x over previous
#include <cuda_runtime.h>

namespace {
constexpr int P    = 32;
constexpr int Cin  = 9;
constexpr int H    = 64;
constexpr int OUTC = 128;
constexpr int FS   = 36;   // fT row stride (floats); 16B-aligned rows
constexpr float EPS = 1e-5f;
}

using ull = unsigned long long;

struct SB {
  float  fT[2][H][FS];     // activations [q][channel][point]; pre-layer overlays ptsT here
  float  mk[2][P];
  float2 pooled2[H];       // {q0,q1} interleaved
  ull    part[2][H];       // split-k partials (pctr / o1)
  float2 pctr2[H];
  float2 feat2[H];
  float2 hid2[H];
  int    s_mode;
  int    s_valid[2];
};

__device__ __forceinline__ ull fma2(ull a, ull b, ull c) {
  ull d;
  asm("fma.rn.f32x2 %0, %1, %2, %3;" : "=l"(d) : "l"(a), "l"(b), "l"(c));
  return d;
}
__device__ __forceinline__ ull dup2(float x) {
  ull d; unsigned u = __float_as_uint(x);
  asm("mov.b64 %0, {%1, %1};" : "=l"(d) : "r"(u));
  return d;
}
__device__ __forceinline__ float2 unpk(ull v) {
  unsigned a, b;
  asm("mov.b64 {%0, %1}, %2;" : "=r"(a), "=r"(b) : "l"(v));
  return make_float2(__uint_as_float(a), __uint_as_float(b));
}
// BN fold, single channel, duplicated into both f32x2 lanes
__device__ __forceinline__ void bn1(const float* g, const float* be,
                                    const float* rm, const float* rv,
                                    const float* b, int h, ull& Ad, ull& Bd) {
  float s = __ldg(&g[h]) * rsqrtf(__ldg(&rv[h]) + EPS);
  float c = (__ldg(&b[h]) - __ldg(&rm[h])) * s + __ldg(&be[h]);
  Ad = dup2(s);
  Bd = dup2(c);
}

// 16 fma2: weights dup'd per channel, x arrives as packed point pairs
#define MMA_K(WV)                                                            \
  {                                                                          \
    ull wd0 = dup2((WV).x), wd1 = dup2((WV).y);                              \
    ull wd2 = dup2((WV).z), wd3 = dup2((WV).w);                              \
    ulonglong2 xa = *(const ulonglong2*)&sb->fT[0][k][p0];                   \
    ulonglong2 xb = *(const ulonglong2*)&sb->fT[1][k][p0];                   \
    acc[0][0][0]=fma2(xa.x,wd0,acc[0][0][0]); acc[0][0][1]=fma2(xa.y,wd0,acc[0][0][1]); \
    acc[0][1][0]=fma2(xa.x,wd1,acc[0][1][0]); acc[0][1][1]=fma2(xa.y,wd1,acc[0][1][1]); \
    acc[0][2][0]=fma2(xa.x,wd2,acc[0][2][0]); acc[0][2][1]=fma2(xa.y,wd2,acc[0][2][1]); \
    acc[0][3][0]=fma2(xa.x,wd3,acc[0][3][0]); acc[0][3][1]=fma2(xa.y,wd3,acc[0][3][1]); \
    acc[1][0][0]=fma2(xb.x,wd0,acc[1][0][0]); acc[1][0][1]=fma2(xb.y,wd0,acc[1][0][1]); \
    acc[1][1][0]=fma2(xb.x,wd1,acc[1][1][0]); acc[1][1][1]=fma2(xb.y,wd1,acc[1][1][1]); \
    acc[1][2][0]=fma2(xb.x,wd2,acc[1][2][0]); acc[1][2][1]=fma2(xb.y,wd2,acc[1][2][1]); \
    acc[1][3][0]=fma2(xb.x,wd3,acc[1][3][0]); acc[1][3][1]=fma2(xb.y,wd3,acc[1][3][1]); \
  }

__global__ void __launch_bounds__(128)
pnet_kernel(const float* __restrict__ poly,
            const void*  __restrict__ mask,
            const float* __restrict__ pre_w, const float* __restrict__ pre_b,
            const float* __restrict__ pre_g, const float* __restrict__ pre_be,
            const float* __restrict__ pre_rm, const float* __restrict__ pre_rv,
            const float* __restrict__ m1_w,  const float* __restrict__ m1_b,
            const float* __restrict__ m1_g,  const float* __restrict__ m1_be,
            const float* __restrict__ m1_rm, const float* __restrict__ m1_rv,
            const float* __restrict__ m2_w,  const float* __restrict__ m2_b,
            const float* __restrict__ m2_g,  const float* __restrict__ m2_be,
            const float* __restrict__ m2_rm, const float* __restrict__ m2_rv,
            const float* __restrict__ o1_w,  const float* __restrict__ o1_b,
            const float* __restrict__ o2_w,  const float* __restrict__ o2_b,
            float* __restrict__ out)
{
  __shared__ __align__(16) SB sbs;
  SB* sb = &sbs;

  const int blk = blockIdx.x;          // polylines 2*blk, 2*blk+1
  const int tid = threadIdx.x;         // 0..127
  const int cg  = tid >> 3;            // 0..15  -> 4 channels each
  const int pg  = tid & 7;             // 0..7   -> 4 points each
  const int h0  = cg * 4;
  const int p0  = pg * 4;

  // ---- mask dtype detection (int32 vs float32 vs byte) ----
  if (tid == 0) {
    const unsigned* w32 = (const unsigned*)mask;
    bool big = false, allf = true;
    #pragma unroll
    for (int i = 0; i < 32; i++) {
      unsigned v = w32[i];
      big  |= (v > 1u);
      allf &= (v == 0u || v == 0x3f800000u);
    }
    sb->s_mode = big ? (allf ? 1 : 2) : 0;
  }
  __syncthreads();
  const int mode = sb->s_mode;

  // ---- load points TRANSPOSED into fT overlay: ptsT[q][c][p] ----
  float* ptsT = (float*)sb->fT;        // 576 floats << fT region
  {
    const float* pp = poly + (long long)(2 * blk) * (P * Cin);
    for (int i = tid; i < 2 * P * Cin; i += 128) {
      int q = i / (P * Cin), r = i % (P * Cin);
      int p = r / Cin, c = r % Cin;
      ptsT[q * 288 + c * 32 + p] = pp[i];
    }
  }
  if (tid < 64) {
    int q = tid >> 5, t = tid & 31;
    int gi = (2 * blk + q) * P + t;
    float mv;
    if (mode == 2)      mv = ((const unsigned char*)mask)[gi] ? 1.f : 0.f;
    else if (mode == 1) mv = (((const float*)mask)[gi] != 0.f) ? 1.f : 0.f;
    else                mv = ((const int*)mask)[gi] ? 1.f : 0.f;
    sb->mk[q][t] = mv;
    unsigned bal = __ballot_sync(0xffffffffu, mv != 0.f);
    if (t == 0) sb->s_valid[q] = (bal != 0u) ? 1 : 0;
  }
  __syncthreads();

  ull acc[2][4][2];    // [q][channel][point-pair]
  ull Ad[4], Bd[4];

  // ================= pre layer: [P,9] @ [9,64] =============================
  #pragma unroll
  for (int q = 0; q < 2; q++)
    #pragma unroll
    for (int c = 0; c < 4; c++) { acc[q][c][0] = 0ull; acc[q][c][1] = 0ull; }

  #pragma unroll 3
  for (int k = 0; k < Cin; k++) {
    float4 wv = __ldg((const float4*)(pre_w + k * H + h0));
    ull wd0 = dup2(wv.x), wd1 = dup2(wv.y), wd2 = dup2(wv.z), wd3 = dup2(wv.w);
    ulonglong2 xa = *(const ulonglong2*)&ptsT[k * 32 + p0];
    ulonglong2 xb = *(const ulonglong2*)&ptsT[288 + k * 32 + p0];
    acc[0][0][0]=fma2(xa.x,wd0,acc[0][0][0]); acc[0][0][1]=fma2(xa.y,wd0,acc[0][0][1]);
    acc[0][1][0]=fma2(xa.x,wd1,acc[0][1][0]); acc[0][1][1]=fma2(xa.y,wd1,acc[0][1][1]);
    acc[0][2][0]=fma2(xa.x,wd2,acc[0][2][0]); acc[0][2][1]=fma2(xa.y,wd2,acc[0][2][1]);
    acc[0][3][0]=fma2(xa.x,wd3,acc[0][3][0]); acc[0][3][1]=fma2(xa.y,wd3,acc[0][3][1]);
    acc[1][0][0]=fma2(xb.x,wd0,acc[1][0][0]); acc[1][0][1]=fma2(xb.y,wd0,acc[1][0][1]);
    acc[1][1][0]=fma2(xb.x,wd1,acc[1][1][0]); acc[1][1][1]=fma2(xb.y,wd1,acc[1][1][1]);
    acc[1][2][0]=fma2(xb.x,wd2,acc[1][2][0]); acc[1][2][1]=fma2(xb.y,wd2,acc[1][2][1]);
    acc[1][3][0]=fma2(xb.x,wd3,acc[1][3][0]); acc[1][3][1]=fma2(xb.y,wd3,acc[1][3][1]);
  }
  #pragma unroll
  for (int c = 0; c < 4; c++) bn1(pre_g, pre_be, pre_rm, pre_rv, pre_b, h0 + c, Ad[c], Bd[c]);
  {
    float4 sv[2][4];
    #pragma unroll
    for (int q = 0; q < 2; q++) {
      float mv0 = sb->mk[q][p0],     mv1 = sb->mk[q][p0 + 1];
      float mv2 = sb->mk[q][p0 + 2], mv3 = sb->mk[q][p0 + 3];
      #pragma unroll
      for (int c = 0; c < 4; c++) {
        float2 rA = unpk(fma2(acc[q][c][0], Ad[c], Bd[c]));
        float2 rB = unpk(fma2(acc[q][c][1], Ad[c], Bd[c]));
        sv[q][c] = make_float4(fmaxf(rA.x, 0.f) * mv0, fmaxf(rA.y, 0.f) * mv1,
                               fmaxf(rB.x, 0.f) * mv2, fmaxf(rB.y, 0.f) * mv3);
      }
    }
    __syncthreads();   // all ptsT reads done before fT overwrite
    #pragma unroll
    for (int q = 0; q < 2; q++)
      #pragma unroll
      for (int c = 0; c < 4; c++)
        *(float4*)&sb->fT[q][h0 + c][p0] = sv[q][c];
  }
  __syncthreads();

  // ===== max-pool over points: thread = (q, channel) =======================
  {
    int q = tid >> 6, ch = tid & 63;
    const float4* row = (const float4*)&sb->fT[q][ch][0];
    float m = 0.f;
    #pragma unroll
    for (int g = 0; g < 8; g++) {
      float4 v = row[g];
      m = fmaxf(m, fmaxf(fmaxf(v.x, v.y), fmaxf(v.z, v.w)));
    }
    (&sb->pooled2[ch].x)[q] = m;
  }
  __syncthreads();

  const ull ONE = dup2(1.f);

  // pctr = pooled @ m1_w[64:128,:], split-k over 2 halves ====================
  {
    int half = tid >> 6, ch = tid & 63;
    int kb = half * 32;
    ull a = 0ull;
    #pragma unroll 8
    for (int k = 0; k < 32; k++) {
      float wv = __ldg(&m1_w[(H + kb + k) * H + ch]);
      a = fma2(*(const ull*)&sb->pooled2[kb + k], dup2(wv), a);
    }
    sb->part[half][ch] = a;
  }
  __syncthreads();
  if (tid < 64) {
    ull s = fma2(sb->part[0][tid], ONE, sb->part[1][tid]);
    float2 r = unpk(s);
    sb->pctr2[tid] = r;
  }
  __syncthreads();

  // ================= m1: [P,64] @ m1_w[0:64,:] + pctr ======================
  #pragma unroll
  for (int c = 0; c < 4; c++) {
    float2 pc = sb->pctr2[h0 + c];
    acc[0][c][0] = acc[0][c][1] = dup2(pc.x);
    acc[1][c][0] = acc[1][c][1] = dup2(pc.y);
  }
  #pragma unroll 4
  for (int k = 0; k < H; k++) {
    float4 wv = __ldg((const float4*)(m1_w + k * H + h0));
    MMA_K(wv)
  }
  #pragma unroll
  for (int c = 0; c < 4; c++) bn1(m1_g, m1_be, m1_rm, m1_rv, m1_b, h0 + c, Ad[c], Bd[c]);
  {
    float4 sv[2][4];
    #pragma unroll
    for (int q = 0; q < 2; q++)
      #pragma unroll
      for (int c = 0; c < 4; c++) {
        float2 rA = unpk(fma2(acc[q][c][0], Ad[c], Bd[c]));
        float2 rB = unpk(fma2(acc[q][c][1], Ad[c], Bd[c]));
        sv[q][c] = make_float4(fmaxf(rA.x, 0.f), fmaxf(rA.y, 0.f),
                               fmaxf(rB.x, 0.f), fmaxf(rB.y, 0.f));
      }
    __syncthreads();   // all fT reads done
    #pragma unroll
    for (int q = 0; q < 2; q++)
      #pragma unroll
      for (int c = 0; c < 4; c++)
        *(float4*)&sb->fT[q][h0 + c][p0] = sv[q][c];
  }
  __syncthreads();

  // ================= m2: [P,64] @ [64,64], masked ==========================
  #pragma unroll
  for (int q = 0; q < 2; q++)
    #pragma unroll
    for (int c = 0; c < 4; c++) { acc[q][c][0] = 0ull; acc[q][c][1] = 0ull; }

  #pragma unroll 4
  for (int k = 0; k < H; k++) {
    float4 wv = __ldg((const float4*)(m2_w + k * H + h0));
    MMA_K(wv)
  }
  #pragma unroll
  for (int c = 0; c < 4; c++) bn1(m2_g, m2_be, m2_rm, m2_rv, m2_b, h0 + c, Ad[c], Bd[c]);
  {
    float4 sv[2][4];
    #pragma unroll
    for (int q = 0; q < 2; q++) {
      float mv0 = sb->mk[q][p0],     mv1 = sb->mk[q][p0 + 1];
      float mv2 = sb->mk[q][p0 + 2], mv3 = sb->mk[q][p0 + 3];
      #pragma unroll
      for (int c = 0; c < 4; c++) {
        float2 rA = unpk(fma2(acc[q][c][0], Ad[c], Bd[c]));
        float2 rB = unpk(fma2(acc[q][c][1], Ad[c], Bd[c]));
        sv[q][c] = make_float4(fmaxf(rA.x, 0.f) * mv0, fmaxf(rA.y, 0.f) * mv1,
                               fmaxf(rB.x, 0.f) * mv2, fmaxf(rB.y, 0.f) * mv3);
      }
    }
    __syncthreads();
    #pragma unroll
    for (int q = 0; q < 2; q++)
      #pragma unroll
      for (int c = 0; c < 4; c++)
        *(float4*)&sb->fT[q][h0 + c][p0] = sv[q][c];
  }
  __syncthreads();

  // ===== feat = max-pool over points =======================================
  {
    int q = tid >> 6, ch = tid & 63;
    const float4* row = (const float4*)&sb->fT[q][ch][0];
    float m = 0.f;
    #pragma unroll
    for (int g = 0; g < 8; g++) {
      float4 v = row[g];
      m = fmaxf(m, fmaxf(fmaxf(v.x, v.y), fmaxf(v.z, v.w)));
    }
    (&sb->feat2[ch].x)[q] = m;
  }
  __syncthreads();

  // ===== head layer 1: hid = relu(feat @ o1_w + o1_b), split-k =============
  {
    int half = tid >> 6, ch = tid & 63;
    int kb = half * 32;
    ull a = 0ull;
    #pragma unroll 8
    for (int k = 0; k < 32; k++) {
      float wv = __ldg(&o1_w[(kb + k) * H + ch]);
      a = fma2(*(const ull*)&sb->feat2[kb + k], dup2(wv), a);
    }
    sb->part[half][ch] = a;
  }
  __syncthreads();
  if (tid < 64) {
    ull s = fma2(sb->part[0][tid], ONE, sb->part[1][tid]);
    s = fma2(dup2(__ldg(&o1_b[tid])), ONE, s);
    float2 r = unpk(s);
    sb->hid2[tid] = make_float2(fmaxf(r.x, 0.f), fmaxf(r.y, 0.f));
  }
  __syncthreads();

  // ===== head layer 2: out = hid @ o2_w + o2_b, j = tid ====================
  {
    float vf0 = sb->s_valid[0] ? 1.f : 0.f;
    float vf1 = sb->s_valid[1] ? 1.f : 0.f;
    ull a = dup2(__ldg(&o2_b[tid]));
    #pragma unroll 8
    for (int k = 0; k < H; k++) {
      float wv = __ldg(&o2_w[k * OUTC + tid]);
      a = fma2(*(const ull*)&sb->hid2[k], dup2(wv), a);
    }
    float2 r = unpk(a);
    out[(long long)(2 * blk) * OUTC + tid]     = r.x * vf0;
    out[(long long)(2 * blk + 1) * OUTC + tid] = r.y * vf1;
  }
}

extern "C" void kernel_launch(void* const* d_in, const int* in_sizes, int n_in,
                              void* d_out, int out_size)
{
  (void)in_sizes; (void)n_in;
  const int n_poly = out_size / OUTC;   // B*N = 16384 (even)
  pnet_kernel<<<n_poly / 2, 128>>>(
      (const float*)d_in[0],  d_in[1],
      (const float*)d_in[2],  (const float*)d_in[3],
      (const float*)d_in[4],  (const float*)d_in[5],
      (const float*)d_in[6],  (const float*)d_in[7],
      (const float*)d_in[8],  (const float*)d_in[9],
      (const float*)d_in[10], (const float*)d_in[11],
      (const float*)d_in[12], (const float*)d_in[13],
      (const float*)d_in[14], (const float*)d_in[15],
      (const float*)d_in[16], (const float*)d_in[17],
      (const float*)d_in[18], (const float*)d_in[19],
      (const float*)d_in[20], (const float*)d_in[21],
      (const float*)d_in[22], (const float*)d_in[23],
      (float*)d_out);
}